// round 3
// baseline (speedup 1.0000x reference)
#include <cuda_runtime.h>
#include <cstdint>
#include <cstddef>

// Problem capacity (actual sizes derived at runtime, bounded by these)
#define NMAX 20000
#define EMAX 320000

// ---------------- scratch (device globals; no allocation allowed) ----------------
__device__ int   g_count[NMAX];
__device__ int   g_offs[NMAX + 1];
__device__ int   g_cursor[NMAX];
__device__ int   g_eidx[EMAX];
__device__ float g_feat1[NMAX * 256];
__device__ float g_el1[NMAX * 4];
__device__ float g_er1[NMAX * 4];
__device__ float g_h2[NMAX * 256];
__device__ float g_feat2[NMAX * 64];
__device__ float g_el2[NMAX];
__device__ float g_er2[NMAX];

// ---------------- packed f32x2 helpers (2x FFMA throughput on sm_103a) -----------
__device__ __forceinline__ unsigned long long pack2(float x, float y) {
    unsigned long long r;
    asm("mov.b64 %0, {%1, %2};" : "=l"(r) : "f"(x), "f"(y));
    return r;
}
__device__ __forceinline__ float2 unpack2(unsigned long long v) {
    float2 r;
    asm("mov.b64 {%0, %1}, %2;" : "=f"(r.x), "=f"(r.y) : "l"(v));
    return r;
}
#define FMA2(d, a, b) asm("fma.rn.f32x2 %0, %1, %2, %0;" : "+l"(d) : "l"(a), "l"(b))

// ---------------- CSR build ------------------------------------------------------
__global__ void zero_count_k(int n) {
    int i = blockIdx.x * blockDim.x + threadIdx.x;
    if (i < n) g_count[i] = 0;
}

__global__ void hist_k(const int* __restrict__ dst, int E) {
    int e = blockIdx.x * blockDim.x + threadIdx.x;
    if (e < E) atomicAdd(&g_count[dst[e]], 1);
}

// single block, 1024 threads: exclusive scan of g_count -> g_offs, copy -> g_cursor
__global__ void scan_k(int n) {
    __shared__ int part[1024];
    int tid = threadIdx.x;
    int per = (n + 1023) >> 10;
    int base = tid * per;
    int sum = 0;
    for (int i = 0; i < per; i++) {
        int idx = base + i;
        if (idx < n) sum += g_count[idx];
    }
    part[tid] = sum;
    __syncthreads();
    for (int off = 1; off < 1024; off <<= 1) {
        int t = (tid >= off) ? part[tid - off] : 0;
        __syncthreads();
        part[tid] += t;
        __syncthreads();
    }
    int run = part[tid] - sum;  // exclusive prefix at base
    for (int i = 0; i < per; i++) {
        int idx = base + i;
        if (idx < n) {
            g_offs[idx] = run;
            g_cursor[idx] = run;
            run += g_count[idx];
        }
    }
    if (tid == 1023) g_offs[n] = part[1023];
}

__global__ void scatter_k(const int* __restrict__ dst, int E) {
    int e = blockIdx.x * blockDim.x + threadIdx.x;
    if (e < E) {
        int p = atomicAdd(&g_cursor[dst[e]], 1);
        g_eidx[p] = e;
    }
}

// ---------------- GEMM: C[N,M] = A[N,K] @ B[K,M], fp32, f32x2-packed -------------
// 64x64 block tile, BK=16, 256 threads, 4x4 per-thread micro-tile.
__global__ __launch_bounds__(256) void gemm_k(const float* __restrict__ A,
                                              const float* __restrict__ B,
                                              float* __restrict__ C,
                                              int N, int K, int M) {
    __shared__ float As[16][64];  // transposed: As[k][row]
    __shared__ float Bs[16][64];
    int tid = threadIdx.x;
    int tr = tid >> 4, tc = tid & 15;
    int rowBase = blockIdx.y * 64, colBase = blockIdx.x * 64;

    unsigned long long acc[4][2];
#pragma unroll
    for (int m = 0; m < 4; m++)
#pragma unroll
        for (int p = 0; p < 2; p++) acc[m][p] = 0ull;  // packed (0.f, 0.f)

    int arow = tid >> 2, ac4 = (tid & 3) << 2;
    int brow = tid >> 4, bc4 = (tid & 15) << 2;
    int grow = rowBase + arow;

    for (int k0 = 0; k0 < K; k0 += 16) {
        float4 av = make_float4(0.f, 0.f, 0.f, 0.f);
        if (grow < N) av = *(const float4*)&A[(size_t)grow * K + k0 + ac4];
        As[ac4 + 0][arow] = av.x;
        As[ac4 + 1][arow] = av.y;
        As[ac4 + 2][arow] = av.z;
        As[ac4 + 3][arow] = av.w;
        *(float4*)&Bs[brow][bc4] = *(const float4*)&B[(size_t)(k0 + brow) * M + colBase + bc4];
        __syncthreads();
#pragma unroll
        for (int k = 0; k < 16; k++) {
            float4 am = *(const float4*)&As[k][tr << 2];
            const unsigned long long* bp = (const unsigned long long*)&Bs[k][tc << 2];
            unsigned long long b0 = bp[0], b1 = bp[1];
            unsigned long long a0 = pack2(am.x, am.x);
            unsigned long long a1 = pack2(am.y, am.y);
            unsigned long long a2 = pack2(am.z, am.z);
            unsigned long long a3 = pack2(am.w, am.w);
            FMA2(acc[0][0], a0, b0); FMA2(acc[0][1], a0, b1);
            FMA2(acc[1][0], a1, b0); FMA2(acc[1][1], a1, b1);
            FMA2(acc[2][0], a2, b0); FMA2(acc[2][1], a2, b1);
            FMA2(acc[3][0], a3, b0); FMA2(acc[3][1], a3, b1);
        }
        __syncthreads();
    }
#pragma unroll
    for (int m = 0; m < 4; m++) {
        int row = rowBase + (tr << 2) + m;
        if (row < N) {
            float2 p0 = unpack2(acc[m][0]);
            float2 p1 = unpack2(acc[m][1]);
            float4 v = make_float4(p0.x, p0.y, p1.x, p1.y);
            *(float4*)&C[(size_t)row * M + colBase + (tc << 2)] = v;
        }
    }
}

// ---------------- attention scores: el[n,h] = feat[n,h,:].al[h,:] ---------------
// one warp per (n,h); feat offset for (n,h) is exactly w*64 where w = n*H+h.
__global__ __launch_bounds__(256) void attn_k(const float* __restrict__ feat,
                       const float* __restrict__ al,
                       const float* __restrict__ ar, float* __restrict__ el,
                       float* __restrict__ er, int N, int H) {
    int w = (blockIdx.x * blockDim.x + threadIdx.x) >> 5;
    int lane = threadIdx.x & 31;
    if (w >= N * H) return;
    int h = w % H;
    const float* f = feat + (size_t)w * 64;
    float x0 = f[lane], x1 = f[lane + 32];
    float sl = x0 * al[h * 64 + lane] + x1 * al[h * 64 + lane + 32];
    float sr = x0 * ar[h * 64 + lane] + x1 * ar[h * 64 + lane + 32];
#pragma unroll
    for (int o = 16; o; o >>= 1) {
        sl += __shfl_xor_sync(0xffffffffu, sl, o);
        sr += __shfl_xor_sync(0xffffffffu, sr, o);
    }
    if (lane == 0) { el[w] = sl; er[w] = sr; }
}

// ---------------- fused per-node softmax + aggregation + bias(+ELU) -------------
// one warp per dst node. pass A: per-head max over in-edges (lane-strided).
// pass B: whole warp walks edges; each lane accumulates F/32 output features;
// denominator accumulated redundantly per-lane. epilogue: /den + bias (+ELU).
template <int H, bool DO_ELU>
__global__ __launch_bounds__(256) void node_agg_k(const float* __restrict__ feat,
                           const float* __restrict__ el,
                           const float* __restrict__ er, const int* __restrict__ src,
                           const float* __restrict__ bias, float* __restrict__ out,
                           int N) {
    constexpr int F = H * 64;
    constexpr int FP = F / 32;  // floats per lane: 8 (H=4) or 2 (H=1)
    int w = (blockIdx.x * blockDim.x + threadIdx.x) >> 5;
    int lane = threadIdx.x & 31;
    if (w >= N) return;
    int beg = g_offs[w], end = g_offs[w + 1];

    float erh[H];
#pragma unroll
    for (int h = 0; h < H; h++) erh[h] = er[w * H + h];

    // ---- pass A: max of leaky_relu(el[src]+er[dst]) per head ----
    float mx[H];
#pragma unroll
    for (int h = 0; h < H; h++) mx[h] = -1e30f;
    for (int i = beg + lane; i < end; i += 32) {
        int e = g_eidx[i];
        int s = src[e];
        if (H == 4) {
            float4 t = *(const float4*)&el[s * 4];
            float ev[4] = {t.x, t.y, t.z, t.w};
#pragma unroll
            for (int h = 0; h < 4; h++) {
                float v = ev[h] + erh[h];
                v = v > 0.f ? v : 0.2f * v;
                mx[h] = fmaxf(mx[h], v);
            }
        } else {
            float v = el[s] + erh[0];
            v = v > 0.f ? v : 0.2f * v;
            mx[0] = fmaxf(mx[0], v);
        }
    }
#pragma unroll
    for (int o = 16; o; o >>= 1)
#pragma unroll
        for (int h = 0; h < H; h++) mx[h] = fmaxf(mx[h], __shfl_xor_sync(0xffffffffu, mx[h], o));

    // ---- pass B: accumulate exp-weights and weighted features ----
    float den[H];
#pragma unroll
    for (int h = 0; h < H; h++) den[h] = 0.f;
    float acc[FP];
#pragma unroll
    for (int j = 0; j < FP; j++) acc[j] = 0.f;
    int hsel = (lane * FP) >> 6;  // head owning this lane's chunk

    for (int i = beg; i < end; i++) {
        int e = g_eidx[i];
        int s = src[e];
        float ex[H];
        if (H == 4) {
            float4 t = *(const float4*)&el[s * 4];
            float ev[4] = {t.x, t.y, t.z, t.w};
#pragma unroll
            for (int h = 0; h < 4; h++) {
                float v = ev[h] + erh[h];
                v = v > 0.f ? v : 0.2f * v;
                ex[h] = __expf(v - mx[h]);
                den[h] += ex[h];
            }
        } else {
            float v = el[s] + erh[0];
            v = v > 0.f ? v : 0.2f * v;
            ex[0] = __expf(v - mx[0]);
            den[0] += ex[0];
        }
        const float* fs = feat + (size_t)s * F + lane * FP;
        if (FP == 8) {
            float4 f0 = *(const float4*)fs;
            float4 f1 = *(const float4*)(fs + 4);
            float a = ex[hsel];
            acc[0] += f0.x * a; acc[1] += f0.y * a; acc[2] += f0.z * a; acc[3] += f0.w * a;
            acc[4] += f1.x * a; acc[5] += f1.y * a; acc[6] += f1.z * a; acc[7] += f1.w * a;
        } else {
            float2 f0 = *(const float2*)fs;
            float a = ex[0];
            acc[0] += f0.x * a;
            acc[1] += f0.y * a;
        }
    }

    float inv = (end > beg) ? 1.f / den[hsel] : 0.f;
    float* po = out + (size_t)w * F + lane * FP;
#pragma unroll
    for (int j = 0; j < FP; j++) {
        float r = acc[j] * inv + bias[lane * FP + j];
        if (DO_ELU) r = r > 0.f ? r : expm1f(r);
        po[j] = r;
    }
}

// ---------------- launch ---------------------------------------------------------
extern "C" void kernel_launch(void* const* d_in, const int* in_sizes, int n_in,
                              void* d_out, int out_size) {
    const float* X   = (const float*)d_in[0];
    const float* W1  = (const float*)d_in[1];
    const float* al1 = (const float*)d_in[2];
    const float* ar1 = (const float*)d_in[3];
    const float* b1  = (const float*)d_in[4];
    const float* W2  = (const float*)d_in[5];
    const float* al2 = (const float*)d_in[6];
    const float* ar2 = (const float*)d_in[7];
    const float* b2  = (const float*)d_in[8];
    const int*   src = (const int*)d_in[9];
    const int*   dst = (const int*)d_in[10];
    float* out = (float*)d_out;

    int N = in_sizes[0] / 256;
    int E = in_sizes[9];

    void *p_feat1, *p_el1, *p_er1, *p_h2, *p_feat2, *p_el2, *p_er2;
    cudaGetSymbolAddress(&p_feat1, g_feat1);
    cudaGetSymbolAddress(&p_el1, g_el1);
    cudaGetSymbolAddress(&p_er1, g_er1);
    cudaGetSymbolAddress(&p_h2, g_h2);
    cudaGetSymbolAddress(&p_feat2, g_feat2);
    cudaGetSymbolAddress(&p_el2, g_el2);
    cudaGetSymbolAddress(&p_er2, g_er2);

    // CSR build
    zero_count_k<<<(N + 255) / 256, 256>>>(N);
    hist_k<<<(E + 255) / 256, 256>>>(dst, E);
    scan_k<<<1, 1024>>>(N);
    scatter_k<<<(E + 255) / 256, 256>>>(dst, E);

    // Layer 1
    gemm_k<<<dim3(256 / 64, (N + 63) / 64), 256>>>(X, W1, (float*)p_feat1, N, 256, 256);
    attn_k<<<(N * 4 * 32 + 255) / 256, 256>>>((const float*)p_feat1, al1, ar1,
                                              (float*)p_el1, (float*)p_er1, N, 4);
    node_agg_k<4, true><<<(N * 32 + 255) / 256, 256>>>(
        (const float*)p_feat1, (const float*)p_el1, (const float*)p_er1, src, b1,
        (float*)p_h2, N);

    // Layer 2
    gemm_k<<<dim3(64 / 64, (N + 63) / 64), 256>>>((const float*)p_h2, W2, (float*)p_feat2,
                                                  N, 256, 64);
    attn_k<<<(N * 32 + 255) / 256, 256>>>((const float*)p_feat2, al2, ar2,
                                          (float*)p_el2, (float*)p_er2, N, 1);
    node_agg_k<1, false><<<(N * 32 + 255) / 256, 256>>>(
        (const float*)p_feat2, (const float*)p_el2, (const float*)p_er2, src, b2, out, N);
}

// round 6
// speedup vs baseline: 1.0847x; 1.0847x over previous
#include <cuda_runtime.h>
#include <cstdint>
#include <cstddef>

#define NMAX 20000
#define EMAX 320000

// ---------------- scratch (device globals; no allocation allowed) ----------------
__device__ int   g_count[NMAX];
__device__ int   g_offs[NMAX + 1];
__device__ int   g_cursor[NMAX];
__device__ int   g_esrc[EMAX];      // CSR payload: src node id per edge slot
__device__ float g_feat1[NMAX * 256];
__device__ float g_el1[NMAX * 4];
__device__ float g_er1[NMAX * 4];
__device__ float g_h2[NMAX * 256];
__device__ float g_feat2[NMAX * 64];
__device__ float g_el2[NMAX];
__device__ float g_er2[NMAX];

// ---------------- packed f32x2 helpers ------------------------------------------
__device__ __forceinline__ unsigned long long pack2(float x, float y) {
    unsigned long long r;
    asm("mov.b64 %0, {%1, %2};" : "=l"(r) : "f"(x), "f"(y));
    return r;
}
__device__ __forceinline__ float2 unpack2(unsigned long long v) {
    float2 r;
    asm("mov.b64 {%0, %1}, %2;" : "=f"(r.x), "=f"(r.y) : "l"(v));
    return r;
}
#define FMA2(d, a, b) asm("fma.rn.f32x2 %0, %1, %2, %0;" : "+l"(d) : "l"(a), "l"(b))

// ---------------- CSR build ------------------------------------------------------
__global__ void hist_k(const int* __restrict__ dst, int E) {
    int e = (blockIdx.x * blockDim.x + threadIdx.x) * 2;
    if (e + 1 < E) {
        int d0 = dst[e], d1 = dst[e + 1];
        atomicAdd(&g_count[d0], 1);
        atomicAdd(&g_count[d1], 1);
    } else if (e < E) {
        atomicAdd(&g_count[dst[e]], 1);
    }
}

__global__ void scan_k(int n) {
    __shared__ int part[1024];
    int tid = threadIdx.x;
    int per = (n + 1023) >> 10;
    int base = tid * per;
    int sum = 0;
    for (int i = 0; i < per; i++) {
        int idx = base + i;
        if (idx < n) sum += g_count[idx];
    }
    part[tid] = sum;
    __syncthreads();
    for (int off = 1; off < 1024; off <<= 1) {
        int t = (tid >= off) ? part[tid - off] : 0;
        __syncthreads();
        part[tid] += t;
        __syncthreads();
    }
    int run = part[tid] - sum;
    for (int i = 0; i < per; i++) {
        int idx = base + i;
        if (idx < n) {
            g_offs[idx] = run;
            g_cursor[idx] = run;
            run += g_count[idx];
        }
    }
    if (tid == 1023) g_offs[n] = part[1023];
}

__global__ void scatter_k(const int* __restrict__ dst, const int* __restrict__ src, int E) {
    int e = (blockIdx.x * blockDim.x + threadIdx.x) * 2;
    if (e + 1 < E) {
        int d0 = dst[e], d1 = dst[e + 1];
        int s0 = src[e], s1 = src[e + 1];
        int p0 = atomicAdd(&g_cursor[d0], 1);
        int p1 = atomicAdd(&g_cursor[d1], 1);
        g_esrc[p0] = s0;
        g_esrc[p1] = s1;
    } else if (e < E) {
        int p = atomicAdd(&g_cursor[dst[e]], 1);
        g_esrc[p] = src[e];
    }
}

// ---------------- GEMM + fused attention-score epilogue --------------------------
// C[N,M] = A[N,K] @ B[K,M]; 64x64 tile, BK=16, 256 thr, 4x4 micro-tile (f32x2).
// Epilogue: each block covers exactly one 64-wide head slice (head = blockIdx.x),
// so it also computes el[n,head] = C_row . al[head], er likewise, via partial dots
// + 16-lane half-warp shfl reduction (threads sharing tr are 16 consecutive tids).
__global__ __launch_bounds__(256) void gemm_attn_k(const float* __restrict__ A,
                                                   const float* __restrict__ B,
                                                   float* __restrict__ C,
                                                   const float* __restrict__ al,
                                                   const float* __restrict__ ar,
                                                   float* __restrict__ el,
                                                   float* __restrict__ er,
                                                   int N, int K, int M) {
    __shared__ float As[16][64];
    __shared__ float Bs[16][64];
    int tid = threadIdx.x;
    int tr = tid >> 4, tc = tid & 15;
    int rowBase = blockIdx.y * 64, colBase = blockIdx.x * 64;

    unsigned long long acc[4][2];
#pragma unroll
    for (int m = 0; m < 4; m++)
#pragma unroll
        for (int p = 0; p < 2; p++) acc[m][p] = 0ull;

    int arow = tid >> 2, ac4 = (tid & 3) << 2;
    int brow = tid >> 4, bc4 = (tid & 15) << 2;
    int grow = rowBase + arow;

    for (int k0 = 0; k0 < K; k0 += 16) {
        float4 av = make_float4(0.f, 0.f, 0.f, 0.f);
        if (grow < N) av = *(const float4*)&A[(size_t)grow * K + k0 + ac4];
        As[ac4 + 0][arow] = av.x;
        As[ac4 + 1][arow] = av.y;
        As[ac4 + 2][arow] = av.z;
        As[ac4 + 3][arow] = av.w;
        *(float4*)&Bs[brow][bc4] = *(const float4*)&B[(size_t)(k0 + brow) * M + colBase + bc4];
        __syncthreads();
#pragma unroll
        for (int k = 0; k < 16; k++) {
            float4 am = *(const float4*)&As[k][tr << 2];
            const unsigned long long* bp = (const unsigned long long*)&Bs[k][tc << 2];
            unsigned long long b0 = bp[0], b1 = bp[1];
            unsigned long long a0 = pack2(am.x, am.x);
            unsigned long long a1 = pack2(am.y, am.y);
            unsigned long long a2 = pack2(am.z, am.z);
            unsigned long long a3 = pack2(am.w, am.w);
            FMA2(acc[0][0], a0, b0); FMA2(acc[0][1], a0, b1);
            FMA2(acc[1][0], a1, b0); FMA2(acc[1][1], a1, b1);
            FMA2(acc[2][0], a2, b0); FMA2(acc[2][1], a2, b1);
            FMA2(acc[3][0], a3, b0); FMA2(acc[3][1], a3, b1);
        }
        __syncthreads();
    }

    // al/ar are [M] floats; this block's 4 cols start at colBase + tc*4
    int c0 = colBase + (tc << 2);
    float al0 = al[c0], al1v = al[c0 + 1], al2v = al[c0 + 2], al3 = al[c0 + 3];
    float ar0 = ar[c0], ar1v = ar[c0 + 1], ar2v = ar[c0 + 2], ar3 = ar[c0 + 3];
    int H = M >> 6;
    int head = blockIdx.x;

#pragma unroll
    for (int m = 0; m < 4; m++) {
        int row = rowBase + (tr << 2) + m;
        float2 p0 = unpack2(acc[m][0]);
        float2 p1 = unpack2(acc[m][1]);
        if (row < N) {
            *(float4*)&C[(size_t)row * M + c0] = make_float4(p0.x, p0.y, p1.x, p1.y);
        }
        float sl = p0.x * al0 + p0.y * al1v + p1.x * al2v + p1.y * al3;
        float sr = p0.x * ar0 + p0.y * ar1v + p1.x * ar2v + p1.y * ar3;
#pragma unroll
        for (int o = 8; o; o >>= 1) {
            sl += __shfl_xor_sync(0xffffffffu, sl, o);
            sr += __shfl_xor_sync(0xffffffffu, sr, o);
        }
        if (tc == 0 && row < N) {
            el[row * H + head] = sl;
            er[row * H + head] = sr;
        }
    }
}

// ---------------- fused per-node softmax + aggregation + bias(+ELU) -------------
template <int H, bool DO_ELU>
__global__ __launch_bounds__(256) void node_agg_k(const float* __restrict__ feat,
                           const float* __restrict__ el,
                           const float* __restrict__ er,
                           const float* __restrict__ bias, float* __restrict__ out,
                           int N) {
    constexpr int F = H * 64;
    constexpr int FP = F / 32;
    int w = (blockIdx.x * blockDim.x + threadIdx.x) >> 5;
    int lane = threadIdx.x & 31;
    if (w >= N) return;
    int beg = g_offs[w], end = g_offs[w + 1];

    float erh[H];
#pragma unroll
    for (int h = 0; h < H; h++) erh[h] = er[w * H + h];

    // ---- pass A: per-head max, lane-parallel over edges ----
    float mx[H];
#pragma unroll
    for (int h = 0; h < H; h++) mx[h] = -1e30f;
    for (int i = beg + lane; i < end; i += 32) {
        int s = g_esrc[i];
        if (H == 4) {
            float4 t = *(const float4*)&el[s * 4];
            float ev[4] = {t.x, t.y, t.z, t.w};
#pragma unroll
            for (int h = 0; h < 4; h++) {
                float v = ev[h] + erh[h];
                v = v > 0.f ? v : 0.2f * v;
                mx[h] = fmaxf(mx[h], v);
            }
        } else {
            float v = el[s] + erh[0];
            v = v > 0.f ? v : 0.2f * v;
            mx[0] = fmaxf(mx[0], v);
        }
    }
#pragma unroll
    for (int o = 16; o; o >>= 1)
#pragma unroll
        for (int h = 0; h < H; h++) mx[h] = fmaxf(mx[h], __shfl_xor_sync(0xffffffffu, mx[h], o));

    // ---- pass B: serial over edges, software-pipelined (prefetch s and el) ----
    float den[H];
#pragma unroll
    for (int h = 0; h < H; h++) den[h] = 0.f;
    float acc[FP];
#pragma unroll
    for (int j = 0; j < FP; j++) acc[j] = 0.f;
    int hsel = (lane * FP) >> 6;

    int sNext = (beg < end) ? g_esrc[beg] : 0;
    float4 tNext = make_float4(0.f, 0.f, 0.f, 0.f);
    float eNext = 0.f;
    if (beg < end) {
        if (H == 4) tNext = *(const float4*)&el[sNext * 4];
        else        eNext = el[sNext];
    }

    for (int i = beg; i < end; i++) {
        int s = sNext;
        float4 t = tNext;
        float es = eNext;
        int inext = i + 1;
        if (inext < end) {
            sNext = g_esrc[inext];
            if (H == 4) tNext = *(const float4*)&el[sNext * 4];
            else        eNext = el[sNext];
        }

        float ex[H];
        if (H == 4) {
            float ev[4] = {t.x, t.y, t.z, t.w};
#pragma unroll
            for (int h = 0; h < 4; h++) {
                float v = ev[h] + erh[h];
                v = v > 0.f ? v : 0.2f * v;
                ex[h] = __expf(v - mx[h]);
                den[h] += ex[h];
            }
        } else {
            float v = es + erh[0];
            v = v > 0.f ? v : 0.2f * v;
            ex[0] = __expf(v - mx[0]);
            den[0] += ex[0];
        }
        const float* fs = feat + (size_t)s * F + lane * FP;
        if (FP == 8) {
            float4 f0 = *(const float4*)fs;
            float4 f1 = *(const float4*)(fs + 4);
            float a = ex[hsel];
            acc[0] += f0.x * a; acc[1] += f0.y * a; acc[2] += f0.z * a; acc[3] += f0.w * a;
            acc[4] += f1.x * a; acc[5] += f1.y * a; acc[6] += f1.z * a; acc[7] += f1.w * a;
        } else {
            float2 f0 = *(const float2*)fs;
            float a = ex[0];
            acc[0] += f0.x * a;
            acc[1] += f0.y * a;
        }
    }

    float inv = (end > beg) ? 1.f / den[hsel] : 0.f;
    float* po = out + (size_t)w * F + lane * FP;
#pragma unroll
    for (int j = 0; j < FP; j++) {
        float r = acc[j] * inv + bias[lane * FP + j];
        if (DO_ELU) r = r > 0.f ? r : expm1f(r);
        po[j] = r;
    }
}

// ---------------- launch ---------------------------------------------------------
extern "C" void kernel_launch(void* const* d_in, const int* in_sizes, int n_in,
                              void* d_out, int out_size) {
    const float* X   = (const float*)d_in[0];
    const float* W1  = (const float*)d_in[1];
    const float* al1 = (const float*)d_in[2];
    const float* ar1 = (const float*)d_in[3];
    const float* b1  = (const float*)d_in[4];
    const float* W2  = (const float*)d_in[5];
    const float* al2 = (const float*)d_in[6];
    const float* ar2 = (const float*)d_in[7];
    const float* b2  = (const float*)d_in[8];
    const int*   src = (const int*)d_in[9];
    const int*   dst = (const int*)d_in[10];
    float* out = (float*)d_out;

    int N = in_sizes[0] / 256;
    int E = in_sizes[9];

    void *p_count, *p_feat1, *p_el1, *p_er1, *p_h2, *p_feat2, *p_el2, *p_er2;
    cudaGetSymbolAddress(&p_count, g_count);
    cudaGetSymbolAddress(&p_feat1, g_feat1);
    cudaGetSymbolAddress(&p_el1, g_el1);
    cudaGetSymbolAddress(&p_er1, g_er1);
    cudaGetSymbolAddress(&p_h2, g_h2);
    cudaGetSymbolAddress(&p_feat2, g_feat2);
    cudaGetSymbolAddress(&p_el2, g_el2);
    cudaGetSymbolAddress(&p_er2, g_er2);

    // CSR build
    cudaMemsetAsync(p_count, 0, (size_t)N * sizeof(int));
    int eThreads = (E + 1) / 2;
    hist_k<<<(eThreads + 255) / 256, 256>>>(dst, E);
    scan_k<<<1, 1024>>>(N);
    scatter_k<<<(eThreads + 255) / 256, 256>>>(dst, src, E);

    // Layer 1: GEMM + fused attention scores
    gemm_attn_k<<<dim3(4, (N + 63) / 64), 256>>>(X, W1, (float*)p_feat1, al1, ar1,
                                                 (float*)p_el1, (float*)p_er1, N, 256, 256);
    node_agg_k<4, true><<<(N * 32 + 255) / 256, 256>>>(
        (const float*)p_feat1, (const float*)p_el1, (const float*)p_er1, b1,
        (float*)p_h2, N);

    // Layer 2
    gemm_attn_k<<<dim3(1, (N + 63) / 64), 256>>>((const float*)p_h2, W2, (float*)p_feat2,
                                                 al2, ar2, (float*)p_el2, (float*)p_er2,
                                                 N, 256, 64);
    node_agg_k<1, false><<<(N * 32 + 255) / 256, 256>>>(
        (const float*)p_feat2, (const float*)p_el2, (const float*)p_er2, b2, out, N);
}